// round 4
// baseline (speedup 1.0000x reference)
#include <cuda_runtime.h>
#include <math.h>

#define Bq   8
#define Sq   1024
#define Eq   256
#define Hq   256
#define H2q  512
#define Cq   64

// ---------------- static device scratch (allocation-free rule) ----------------
__device__ __align__(16) float g_x    [Bq*Sq*Eq];
__device__ __align__(16) float g_xgf  [Bq*Sq*3*Hq];
__device__ __align__(16) float g_xgb  [Bq*Sq*3*Hq];
__device__ __align__(16) float g_bigru[Bq*Sq*H2q];
__device__ __align__(16) float g_xgu  [Bq*Sq*3*H2q];
__device__ __align__(16) float g_U    [Bq*Sq*H2q];
__device__ __align__(16) float g_energ[Bq*Sq*Sq];
__device__ __align__(16) float g_ctx  [Bq*Sq*H2q];
__device__ __align__(16) float g_cfc  [Bq*Sq*H2q];
__device__ __align__(16) float g_cfcfc[Bq*Sq*H2q];
__device__ __align__(16) float g_htfc [Bq*Sq*H2q];
__device__ __align__(16) float g_ft   [Bq*Sq*H2q];

__device__ __align__(16) float g_hf[2][Hq*8];
__device__ __align__(16) float g_hb[2][Hq*8];
__device__ __align__(16) float g_hu[2][H2q*8];

__device__ int      g_cnt[4];
__device__ unsigned g_gen[4];

// ---------------- generation-counting grid barrier (BOUNDED spin) ----------------
// If co-residency/visibility ever breaks, the bounded spin guarantees forward
// progress (wrong answer instead of a hung container).
__device__ __forceinline__ void grid_barrier(int idx, int bar_n) {
    __threadfence();
    __syncthreads();
    if (threadIdx.x == 0) {
        volatile unsigned* gv = &g_gen[idx];
        unsigned g = *gv;
        if (atomicAdd(&g_cnt[idx], 1) == bar_n - 1) {
            g_cnt[idx] = 0;
            __threadfence();
            *gv = g + 1;
        } else {
            for (unsigned spin = 0; *gv == g && spin < (1u << 21); ++spin)
                __nanosleep(64);
        }
    }
    __syncthreads();
}

// ---------------- persistent GRU scan worker ----------------
// K = hidden width. 8 outputs j per CTA. 192 thr: tid = q*24 + (j*3+gate).
// Recurrent weights register-resident; h staged to smem [k][b] each step.
template<int K>
__device__ __forceinline__ void scan_worker(
    int j0,
    const float* __restrict__ xg,     // [B*S][3K] (includes input bias)
    const float* __restrict__ wh,     // [3K][K]
    const float* __restrict__ bh,     // [3K]
    float* hA, float* hB,             // ping-pong [K*8] ([k][b])
    float* __restrict__ outbase, int out_off,
    int reverse_time, int bar_idx, int bar_n,
    float* u0base, int u0_off,
    int shift_out)
{
    constexpr int QS = K / 8;
    const int tid = threadIdx.x;
    const int q   = tid / 24;
    const int row = tid % 24;
    const int j   = row / 3;
    const int gg  = row % 3;
    const int jg  = j0 + j;

    float wreg[QS];
    {
        const float* wrow = wh + (size_t)(gg * K + jg) * K + q * QS;
#pragma unroll
        for (int i = 0; i < QS; i++) wreg[i] = wrow[i];
    }

    __shared__ float4 h4[K * 2];
    __shared__ float  part[8 * 192];

    for (int i = tid; i < K * 8; i += 192) hA[i] = 0.f;

    float bhr = 0.f, bhz = 0.f, bhn = 0.f;
    int fb = 0, fjg = 0, fj = 0;
    if (tid < 64) {
        fb  = tid & 7;
        fj  = tid >> 3;
        fjg = j0 + fj;
        bhr = bh[0 * K + fjg];
        bhz = bh[1 * K + fjg];
        bhn = bh[2 * K + fjg];
    }
    grid_barrier(bar_idx, bar_n);

    float* hsrc = hA;
    float* hdst = hB;
    for (int s = 0; s < Sq; s++) {
        const int t = reverse_time ? (Sq - 1 - s) : s;

        for (int i = tid; i < K * 2; i += 192)
            h4[i] = __ldcg(((const float4*)hsrc) + i);
        __syncthreads();

        float acc[8];
#pragma unroll
        for (int b = 0; b < 8; b++) acc[b] = 0.f;
        const int kb = q * QS;
#pragma unroll
        for (int i = 0; i < QS; i++) {
            const float  w  = wreg[i];
            const float4 lo = h4[(kb + i) * 2];
            const float4 hi = h4[(kb + i) * 2 + 1];
            acc[0] += w * lo.x; acc[1] += w * lo.y;
            acc[2] += w * lo.z; acc[3] += w * lo.w;
            acc[4] += w * hi.x; acc[5] += w * hi.y;
            acc[6] += w * hi.z; acc[7] += w * hi.w;
        }
#pragma unroll
        for (int b = 0; b < 8; b++) part[b * 192 + q * 24 + row] = acc[b];
        __syncthreads();

        if (tid < 64) {
            float sr = 0.f, sz = 0.f, sn = 0.f;
#pragma unroll
            for (int qq = 0; qq < 8; qq++) {
                const float* p = &part[fb * 192 + qq * 24 + fj * 3];
                sr += p[0]; sz += p[1]; sn += p[2];
            }
            const float* xr  = xg + ((size_t)fb * Sq + t) * (3 * K);
            const float  xgr = xr[fjg];
            const float  xgz = xr[K + fjg];
            const float  xgn = xr[2 * K + fjg];
            const float  hold = ((const float*)h4)[fjg * 8 + fb];

            const float r  = 1.f / (1.f + expf(-(xgr + sr + bhr)));
            const float z  = 1.f / (1.f + expf(-(xgz + sz + bhz)));
            const float nn = tanhf(xgn + r * (sn + bhn));
            const float hnew = (1.f - z) * nn + z * hold;

            __stcg(&hdst[fjg * 8 + fb], hnew);
            const int to = shift_out ? (t + 1) : t;
            if (to < Sq)
                outbase[((size_t)fb * Sq + to) * H2q + out_off + fjg] = hnew;
            if (s == Sq - 1 && u0base)
                u0base[((size_t)fb * Sq) * H2q + u0_off + fjg] = hnew;
        }
        grid_barrier(bar_idx, bar_n);
        float* tmp = hsrc; hsrc = hdst; hdst = tmp;
    }
}

__global__ void __launch_bounds__(192, 1)
scan_fb(const float* xgf, const float* xgb,
        const float* whf, const float* bhf,
        const float* whb, const float* bhb)
{
    const int  cta = blockIdx.x;
    const bool isb = cta >= 32;
    scan_worker<Hq>((isb ? cta - 32 : cta) * 8,
                    isb ? xgb : xgf,
                    isb ? whb : whf,
                    isb ? bhb : bhf,
                    isb ? g_hb[0] : g_hf[0],
                    isb ? g_hb[1] : g_hf[1],
                    g_bigru, isb ? Hq : 0,
                    isb ? 1 : 0,
                    isb ? 1 : 0, 32,
                    g_U, isb ? 0 : Hq,   // hidden_cat = [hT_b | hT_f]
                    0);
}

__global__ void __launch_bounds__(192, 1)
scan_uni(const float* xgu, const float* whu, const float* bhu)
{
    scan_worker<H2q>(blockIdx.x * 8, xgu, whu, bhu,
                     g_hu[0], g_hu[1],
                     g_U, 0,
                     0, 2, 64,
                     nullptr, 0,
                     1);                 // U[:, t+1] = uni_out[:, t]
}

// ---------------- GEMM: C = A @ W^T + bias ----------------
__global__ void __launch_bounds__(256, 1)
gemm_abt(const float* __restrict__ A, const float* __restrict__ W,
         const float* __restrict__ bias, float* __restrict__ C,
         int M, int N, int K,
         long long sA, long long sW, long long sC)
{
    A += (size_t)blockIdx.z * sA;
    W += (size_t)blockIdx.z * sW;
    C += (size_t)blockIdx.z * sC;

    __shared__ float As[8][132];
    __shared__ float Ws[8][132];

    const int tid = threadIdx.x;
    const int tx = tid % 16, ty = tid / 16;
    const int m0 = blockIdx.y * 128, n0 = blockIdx.x * 128;
    const int r = tid >> 1, cq = tid & 1;

    const float* Aptr = A + (size_t)(m0 + r) * K + cq * 4;
    const bool   wok  = (n0 + r) < N;
    const float* Wptr = W + (size_t)(n0 + r) * K + cq * 4;

    float acc[8][8];
#pragma unroll
    for (int i = 0; i < 8; i++)
#pragma unroll
        for (int jj = 0; jj < 8; jj++) acc[i][jj] = 0.f;

    for (int k0 = 0; k0 < K; k0 += 8) {
        const float4 a4 = *(const float4*)(Aptr + k0);
        const float4 w4 = wok ? *(const float4*)(Wptr + k0)
                              : make_float4(0.f, 0.f, 0.f, 0.f);
        __syncthreads();
        As[cq * 4 + 0][r] = a4.x; As[cq * 4 + 1][r] = a4.y;
        As[cq * 4 + 2][r] = a4.z; As[cq * 4 + 3][r] = a4.w;
        Ws[cq * 4 + 0][r] = w4.x; Ws[cq * 4 + 1][r] = w4.y;
        Ws[cq * 4 + 2][r] = w4.z; Ws[cq * 4 + 3][r] = w4.w;
        __syncthreads();
#pragma unroll
        for (int k = 0; k < 8; k++) {
            float mreg[8], nreg[8];
            *(float4*)&mreg[0] = *(const float4*)&As[k][ty * 8];
            *(float4*)&mreg[4] = *(const float4*)&As[k][ty * 8 + 4];
            *(float4*)&nreg[0] = *(const float4*)&Ws[k][tx * 8];
            *(float4*)&nreg[4] = *(const float4*)&Ws[k][tx * 8 + 4];
#pragma unroll
            for (int i = 0; i < 8; i++)
#pragma unroll
                for (int jj = 0; jj < 8; jj++)
                    acc[i][jj] += mreg[i] * nreg[jj];
        }
    }

    float breg[8];
#pragma unroll
    for (int jj = 0; jj < 8; jj++) {
        const int c = n0 + tx * 8 + jj;
        breg[jj] = (bias && c < N) ? bias[c] : 0.f;
    }
    const int c0 = n0 + tx * 8;
#pragma unroll
    for (int i = 0; i < 8; i++) {
        float* crow = C + (size_t)(m0 + ty * 8 + i) * N;
        if (c0 < N) {
            float4 o = { acc[i][0] + breg[0], acc[i][1] + breg[1],
                         acc[i][2] + breg[2], acc[i][3] + breg[3] };
            *(float4*)(crow + c0) = o;
        }
        if (c0 + 4 < N) {
            float4 o = { acc[i][4] + breg[4], acc[i][5] + breg[5],
                         acc[i][6] + breg[6], acc[i][7] + breg[7] };
            *(float4*)(crow + c0 + 4) = o;
        }
    }
}

// ---------------- GEMM: C = A @ B + bias ----------------
__global__ void __launch_bounds__(256, 1)
gemm_ab(const float* __restrict__ A, const float* __restrict__ B,
        const float* __restrict__ bias, float* __restrict__ C,
        int M, int N, int K,
        long long sA, long long sB, long long sC)
{
    A += (size_t)blockIdx.z * sA;
    B += (size_t)blockIdx.z * sB;
    C += (size_t)blockIdx.z * sC;

    __shared__ float As[8][132];
    __shared__ float Bs[8][132];

    const int tid = threadIdx.x;
    const int tx = tid % 16, ty = tid / 16;
    const int m0 = blockIdx.y * 128, n0 = blockIdx.x * 128;
    const int r = tid >> 1, cq = tid & 1;
    const int kk = tid >> 5, nq = tid & 31;

    const float* Aptr = A + (size_t)(m0 + r) * K + cq * 4;
    const bool   bok  = (n0 + nq * 4) < N;
    const float* Bptr = B + (size_t)kk * N + n0 + nq * 4;

    float acc[8][8];
#pragma unroll
    for (int i = 0; i < 8; i++)
#pragma unroll
        for (int jj = 0; jj < 8; jj++) acc[i][jj] = 0.f;

    for (int k0 = 0; k0 < K; k0 += 8) {
        const float4 a4 = *(const float4*)(Aptr + k0);
        const float4 b4 = bok ? *(const float4*)(Bptr + (size_t)k0 * N)
                              : make_float4(0.f, 0.f, 0.f, 0.f);
        __syncthreads();
        As[cq * 4 + 0][r] = a4.x; As[cq * 4 + 1][r] = a4.y;
        As[cq * 4 + 2][r] = a4.z; As[cq * 4 + 3][r] = a4.w;
        *(float4*)&Bs[kk][nq * 4] = b4;
        __syncthreads();
#pragma unroll
        for (int k = 0; k < 8; k++) {
            float mreg[8], nreg[8];
            *(float4*)&mreg[0] = *(const float4*)&As[k][ty * 8];
            *(float4*)&mreg[4] = *(const float4*)&As[k][ty * 8 + 4];
            *(float4*)&nreg[0] = *(const float4*)&Bs[k][tx * 8];
            *(float4*)&nreg[4] = *(const float4*)&Bs[k][tx * 8 + 4];
#pragma unroll
            for (int i = 0; i < 8; i++)
#pragma unroll
                for (int jj = 0; jj < 8; jj++)
                    acc[i][jj] += mreg[i] * nreg[jj];
        }
    }

    float breg[8];
#pragma unroll
    for (int jj = 0; jj < 8; jj++) {
        const int c = n0 + tx * 8 + jj;
        breg[jj] = (bias && c < N) ? bias[c] : 0.f;
    }
    const int c0 = n0 + tx * 8;
#pragma unroll
    for (int i = 0; i < 8; i++) {
        float* crow = C + (size_t)(m0 + ty * 8 + i) * N;
        if (c0 < N) {
            float4 o = { acc[i][0] + breg[0], acc[i][1] + breg[1],
                         acc[i][2] + breg[2], acc[i][3] + breg[3] };
            *(float4*)(crow + c0) = o;
        }
        if (c0 + 4 < N) {
            float4 o = { acc[i][4] + breg[4], acc[i][5] + breg[5],
                         acc[i][6] + breg[6], acc[i][7] + breg[7] };
            *(float4*)(crow + c0 + 4) = o;
        }
    }
}

// ---------------- row softmax over 1024 cols ----------------
__global__ void __launch_bounds__(256, 1)
softmax_rows(float* __restrict__ E)
{
    float4* e4 = (float4*)(E + (size_t)blockIdx.x * Sq);
    const int tid = threadIdx.x;
    float4 v = e4[tid];

    float m = fmaxf(fmaxf(v.x, v.y), fmaxf(v.z, v.w));
#pragma unroll
    for (int o = 16; o > 0; o >>= 1)
        m = fmaxf(m, __shfl_xor_sync(0xffffffffu, m, o));
    __shared__ float wredm[8];
    if ((tid & 31) == 0) wredm[tid >> 5] = m;
    __syncthreads();
    float mm = wredm[0];
#pragma unroll
    for (int i = 1; i < 8; i++) mm = fmaxf(mm, wredm[i]);

    v.x = expf(v.x - mm); v.y = expf(v.y - mm);
    v.z = expf(v.z - mm); v.w = expf(v.w - mm);
    float s = v.x + v.y + v.z + v.w;
#pragma unroll
    for (int o = 16; o > 0; o >>= 1)
        s += __shfl_xor_sync(0xffffffffu, s, o);
    __shared__ float wreds[8];
    if ((tid & 31) == 0) wreds[tid >> 5] = s;
    __syncthreads();
    float ss = 0.f;
#pragma unroll
    for (int i = 0; i < 8; i++) ss += wreds[i];

    const float inv = 1.f / ss;
    v.x *= inv; v.y *= inv; v.z *= inv; v.w *= inv;
    e4[tid] = v;
}

__global__ void embed_k(const int* __restrict__ tok, const float* __restrict__ emb)
{
    const int i = blockIdx.x * blockDim.x + threadIdx.x;
    const int n4 = Bq * Sq * Eq / 4;
    if (i < n4) {
        const int row = i / (Eq / 4);
        const int c   = i % (Eq / 4);
        const int t   = tok[row];
        ((float4*)g_x)[i] = ((const float4*)(emb + (size_t)t * Eq))[c];
    }
}

__global__ void ft_k()
{
    const int i = blockIdx.x * blockDim.x + threadIdx.x;
    const int n4 = Bq * Sq * H2q / 4;
    if (i < n4) {
        const float4 a = ((const float4*)g_cfc)[i];
        const float4 b = ((const float4*)g_cfcfc)[i];
        const float4 c = ((const float4*)g_htfc)[i];
        const float4 d = ((const float4*)g_bigru)[i];
        float4 o;
        o.x = a.x / (1.f + expf(-(b.x + c.x))) + d.x;
        o.y = a.y / (1.f + expf(-(b.y + c.y))) + d.y;
        o.z = a.z / (1.f + expf(-(b.z + c.z))) + d.z;
        o.w = a.w / (1.f + expf(-(b.w + c.w))) + d.w;
        ((float4*)g_ft)[i] = o;
    }
}

// ---------------- launch ----------------
static float* sym(const void* s) {
    void* p = nullptr;
    cudaGetSymbolAddress(&p, s);
    return (float*)p;
}

extern "C" void kernel_launch(void* const* d_in, const int* in_sizes, int n_in,
                              void* d_out, int out_size)
{
    (void)in_sizes; (void)n_in; (void)out_size;
    const int*   tok     = (const int*)  d_in[0];
    const float* emb     = (const float*)d_in[2];
    const float* wi_f    = (const float*)d_in[3];
    const float* wh_f    = (const float*)d_in[4];
    const float* bi_f    = (const float*)d_in[5];
    const float* bh_f    = (const float*)d_in[6];
    const float* wi_b    = (const float*)d_in[7];
    const float* wh_b    = (const float*)d_in[8];
    const float* bi_b    = (const float*)d_in[9];
    const float* bh_b    = (const float*)d_in[10];
    const float* uwi     = (const float*)d_in[11];
    const float* uwh     = (const float*)d_in[12];
    const float* ubi     = (const float*)d_in[13];
    const float* ubh     = (const float*)d_in[14];
    const float* w_attn  = (const float*)d_in[15];
    const float* b_attn  = (const float*)d_in[16];
    const float* w_afc   = (const float*)d_in[17];
    const float* b_afc   = (const float*)d_in[18];
    const float* w_ht    = (const float*)d_in[19];
    const float* b_ht    = (const float*)d_in[20];
    const float* w_out   = (const float*)d_in[21];
    const float* b_out   = (const float*)d_in[22];
    float* out = (float*)d_out;

    float* x     = sym(g_x);
    float* xgf   = sym(g_xgf);
    float* xgb   = sym(g_xgb);
    float* bigru = sym(g_bigru);
    float* xgu   = sym(g_xgu);
    float* U     = sym(g_U);
    float* energ = sym(g_energ);
    float* ctx   = sym(g_ctx);
    float* cfc   = sym(g_cfc);
    float* cfcfc = sym(g_cfcfc);
    float* htfc  = sym(g_htfc);
    float* ft    = sym(g_ft);

    const long long sU = (long long)Sq * H2q;   // per-batch strides
    const long long sE = (long long)Sq * Sq;
    const int M = Bq * Sq;                      // 8192

    embed_k<<<(Bq*Sq*Eq/4 + 255)/256, 256>>>(tok, emb);

    gemm_abt<<<dim3(6, 64, 1), 256>>>(x, wi_f, bi_f, xgf, M, 3*Hq, Eq, 0, 0, 0);
    gemm_abt<<<dim3(6, 64, 1), 256>>>(x, wi_b, bi_b, xgb, M, 3*Hq, Eq, 0, 0, 0);

    scan_fb<<<64, 192>>>(xgf, xgb, wh_f, bh_f, wh_b, bh_b);

    gemm_abt<<<dim3(12, 64, 1), 256>>>(bigru, uwi, ubi, xgu, M, 3*H2q, H2q, 0, 0, 0);

    scan_uni<<<64, 192>>>(xgu, uwh, ubh);

    gemm_abt<<<dim3(8, 8, Bq), 256>>>(U, bigru, nullptr, energ,
                                      Sq, Sq, H2q, sU, sU, sE);
    softmax_rows<<<M, 256>>>(energ);
    gemm_ab<<<dim3(4, 8, Bq), 256>>>(energ, bigru, nullptr, ctx,
                                     Sq, H2q, Sq, sE, sU, sU);

    gemm_abt<<<dim3(4, 64, 1), 256>>>(ctx,   w_attn, b_attn, cfc,   M, H2q, H2q, 0, 0, 0);
    gemm_abt<<<dim3(4, 64, 1), 256>>>(cfc,   w_afc,  b_afc,  cfcfc, M, H2q, H2q, 0, 0, 0);
    gemm_abt<<<dim3(4, 64, 1), 256>>>(bigru, w_ht,   b_ht,   htfc,  M, H2q, H2q, 0, 0, 0);

    ft_k<<<(Bq*Sq*H2q/4 + 255)/256, 256>>>();

    gemm_abt<<<dim3(1, 64, 1), 256>>>(ft, w_out, b_out, out, M, Cq, H2q, 0, 0, 0);
}

// round 5
// speedup vs baseline: 1.0922x; 1.0922x over previous
#include <cuda_runtime.h>
#include <math.h>

#define Bq   8
#define Sq   1024
#define Eq   256
#define Hq   256
#define H2q  512
#define Cq   64

// ---------------- static device scratch ----------------
__device__ __align__(16) float g_x    [Bq*Sq*Eq];
__device__ __align__(16) float g_xgf  [Bq*Sq*3*Hq];
__device__ __align__(16) float g_xgb  [Bq*Sq*3*Hq];
__device__ __align__(16) float g_bigru[Bq*Sq*H2q];
__device__ __align__(16) float g_xgu  [Bq*Sq*3*H2q];
__device__ __align__(16) float g_U    [Bq*Sq*H2q];
__device__ __align__(16) float g_energ[Bq*Sq*Sq];
__device__ __align__(16) float g_ctx  [Bq*Sq*H2q];
__device__ __align__(16) float g_cfc  [Bq*Sq*H2q];
__device__ __align__(16) float g_cfcfc[Bq*Sq*H2q];
__device__ __align__(16) float g_htfc [Bq*Sq*H2q];
__device__ __align__(16) float g_ft   [Bq*Sq*H2q];

__device__ __align__(16) float g_hf[2][Hq*8];
__device__ __align__(16) float g_hb[2][Hq*8];
__device__ __align__(16) float g_hu[2][H2q*8];

__device__ int      g_cnt[4];
__device__ unsigned g_gen[4];

// ---------------- fast activations (2-ulp __expf; rel err ~1e-7) ----------------
__device__ __forceinline__ float fsig(float x) {
    return __fdividef(1.f, 1.f + __expf(-x));
}
__device__ __forceinline__ float ftanh(float x) {
    // tanh(x) = 1 - 2/(exp(2x)+1); saturates correctly at +-inf
    return 1.f - __fdividef(2.f, __expf(2.f * x) + 1.f);
}

// ---------------- grid barrier (callers fence their own stores) ----------------
__device__ __forceinline__ void grid_barrier_nf(int idx, int bar_n) {
    __syncthreads();
    if (threadIdx.x == 0) {
        volatile unsigned* gv = &g_gen[idx];
        unsigned g = *gv;
        if (atomicAdd(&g_cnt[idx], 1) == bar_n - 1) {
            g_cnt[idx] = 0;
            __threadfence();
            *gv = g + 1;
        } else {
            unsigned spin = 0;
            while (*gv == g) {
                if (++spin > 1024u) {
                    __nanosleep(64);
                    if (spin > (1u << 22)) break;   // hang-proofing
                }
            }
        }
    }
    __syncthreads();
}

// ---------------- persistent GRU scan worker ----------------
// 4 outputs j per CTA. 192 thr: tid = q*12 + (j*3+gate), q in [0,16).
// Recurrent weights register-resident; h staged to smem [k][b] each step.
template<int K>
__device__ __forceinline__ void scan_worker(
    int j0,
    const float* __restrict__ xg,     // [B*S][3K] (includes input bias)
    const float* __restrict__ wh,     // [3K][K]
    const float* __restrict__ bh,     // [3K]
    float* hA, float* hB,             // ping-pong [K*8] ([k][b])
    float* __restrict__ outbase, int out_off,
    int reverse_time, int bar_idx, int bar_n,
    float* u0base, int u0_off,
    int shift_out)
{
    constexpr int ROWS = 12;          // 4 j * 3 gates
    constexpr int Q    = 16;          // k-slices
    constexpr int QS   = K / Q;
    const int tid = threadIdx.x;
    const int q   = tid / ROWS;
    const int row = tid % ROWS;
    const int gg  = row % 3;
    const int jg  = j0 + row / 3;

    float wreg[QS];
    {
        const float* wrow = wh + (size_t)(gg * K + jg) * K + q * QS;
#pragma unroll
        for (int i = 0; i < QS; i++) wreg[i] = wrow[i];
    }

    __shared__ float4 h4[K * 2];
    __shared__ float  part[8 * 193];  // stride 193: bank-conflict-free reduce

    for (int i = tid; i < K * 8; i += 192) { __stcg(&hA[i], 0.f); }

    float bhr = 0.f, bhz = 0.f, bhn = 0.f;
    int fb = 0, fjg = 0, fj = 0;
    if (tid < 32) {
        fb  = tid & 7;
        fj  = tid >> 3;               // 0..3
        fjg = j0 + fj;
        bhr = bh[0 * K + fjg];
        bhz = bh[1 * K + fjg];
        bhn = bh[2 * K + fjg];
    }
    __threadfence();
    grid_barrier_nf(bar_idx, bar_n);

    float* hsrc = hA;
    float* hdst = hB;
    for (int s = 0; s < Sq; s++) {
        const int t = reverse_time ? (Sq - 1 - s) : s;

        // prefetch this step's xg early (off the critical tail)
        float xgr = 0.f, xgz = 0.f, xgn = 0.f;
        if (tid < 32) {
            const float* xr = xg + ((size_t)fb * Sq + t) * (3 * K);
            xgr = __ldg(xr + fjg);
            xgz = __ldg(xr + K + fjg);
            xgn = __ldg(xr + 2 * K + fjg);
        }

        // stage h (L2 -> smem, bypass L1)
        for (int i = tid; i < K * 2; i += 192)
            h4[i] = __ldcg(((const float4*)hsrc) + i);
        __syncthreads();

        float acc[8];
#pragma unroll
        for (int b = 0; b < 8; b++) acc[b] = 0.f;
        const int kb = q * QS;
#pragma unroll
        for (int i = 0; i < QS; i++) {
            const float  w  = wreg[i];
            const float4 lo = h4[(kb + i) * 2];
            const float4 hi = h4[(kb + i) * 2 + 1];
            acc[0] += w * lo.x; acc[1] += w * lo.y;
            acc[2] += w * lo.z; acc[3] += w * lo.w;
            acc[4] += w * hi.x; acc[5] += w * hi.y;
            acc[6] += w * hi.z; acc[7] += w * hi.w;
        }
#pragma unroll
        for (int b = 0; b < 8; b++) part[b * 193 + q * ROWS + row] = acc[b];
        __syncthreads();

        if (tid < 32) {
            float sr = 0.f, sz = 0.f, sn = 0.f;
#pragma unroll
            for (int qq = 0; qq < Q; qq++) {
                const float* p = &part[fb * 193 + qq * ROWS + fj * 3];
                sr += p[0]; sz += p[1]; sn += p[2];
            }
            const float hold = ((const float*)h4)[fjg * 8 + fb];

            const float r    = fsig(xgr + sr + bhr);
            const float z    = fsig(xgz + sz + bhz);
            const float nn   = ftanh(xgn + r * (sn + bhn));
            const float hnew = (1.f - z) * nn + z * hold;

            __stcg(&hdst[fjg * 8 + fb], hnew);
            const int to = shift_out ? (t + 1) : t;
            if (to < Sq)
                outbase[((size_t)fb * Sq + to) * H2q + out_off + fjg] = hnew;
            if (s == Sq - 1 && u0base)
                u0base[((size_t)fb * Sq) * H2q + u0_off + fjg] = hnew;
            __threadfence();   // producer warp only
        }
        grid_barrier_nf(bar_idx, bar_n);
        float* tmp = hsrc; hsrc = hdst; hdst = tmp;
    }
}

// fwd = CTAs [0,64) (bar 0), bwd = CTAs [64,128) (bar 1); run concurrently.
__global__ void __launch_bounds__(192, 1)
scan_fb(const float* xgf, const float* xgb,
        const float* whf, const float* bhf,
        const float* whb, const float* bhb)
{
    const int  cta = blockIdx.x;
    const bool isb = cta >= 64;
    scan_worker<Hq>((isb ? cta - 64 : cta) * 4,
                    isb ? xgb : xgf,
                    isb ? whb : whf,
                    isb ? bhb : bhf,
                    isb ? g_hb[0] : g_hf[0],
                    isb ? g_hb[1] : g_hf[1],
                    g_bigru, isb ? Hq : 0,
                    isb ? 1 : 0,
                    isb ? 1 : 0, 64,
                    g_U, isb ? 0 : Hq,   // hidden_cat = [hT_b | hT_f]
                    0);
}

__global__ void __launch_bounds__(192, 1)
scan_uni(const float* xgu, const float* whu, const float* bhu)
{
    scan_worker<H2q>(blockIdx.x * 4, xgu, whu, bhu,
                     g_hu[0], g_hu[1],
                     g_U, 0,
                     0, 2, 128,
                     nullptr, 0,
                     1);                 // U[:, t+1] = uni_out[:, t]
}

// ---------------- GEMM: C = A @ W^T + bias (pipelined, occ 2) ----------------
__global__ void __launch_bounds__(256, 2)
gemm_abt(const float* __restrict__ A, const float* __restrict__ W,
         const float* __restrict__ bias, float* __restrict__ C,
         int M, int N, int K,
         long long sA, long long sW, long long sC)
{
    A += (size_t)blockIdx.z * sA;
    W += (size_t)blockIdx.z * sW;
    C += (size_t)blockIdx.z * sC;

    __shared__ float As[8][132];
    __shared__ float Ws[8][132];

    const int tid = threadIdx.x;
    const int tx = tid % 16, ty = tid / 16;
    const int m0 = blockIdx.y * 128, n0 = blockIdx.x * 128;
    const int r = tid >> 1, cq = tid & 1;

    const float* Aptr = A + (size_t)(m0 + r) * K + cq * 4;
    const bool   wok  = (n0 + r) < N;
    const float* Wptr = W + (size_t)(n0 + r) * K + cq * 4;

    float acc[8][8];
#pragma unroll
    for (int i = 0; i < 8; i++)
#pragma unroll
        for (int jj = 0; jj < 8; jj++) acc[i][jj] = 0.f;

    float4 a4 = *(const float4*)(Aptr);
    float4 w4 = wok ? *(const float4*)(Wptr) : make_float4(0.f,0.f,0.f,0.f);

    for (int k0 = 0; k0 < K; k0 += 8) {
        __syncthreads();
        As[cq * 4 + 0][r] = a4.x; As[cq * 4 + 1][r] = a4.y;
        As[cq * 4 + 2][r] = a4.z; As[cq * 4 + 3][r] = a4.w;
        Ws[cq * 4 + 0][r] = w4.x; Ws[cq * 4 + 1][r] = w4.y;
        Ws[cq * 4 + 2][r] = w4.z; Ws[cq * 4 + 3][r] = w4.w;
        __syncthreads();
        if (k0 + 8 < K) {   // prefetch next tile during compute
            a4 = *(const float4*)(Aptr + k0 + 8);
            w4 = wok ? *(const float4*)(Wptr + k0 + 8) : make_float4(0.f,0.f,0.f,0.f);
        }
#pragma unroll
        for (int k = 0; k < 8; k++) {
            float mreg[8], nreg[8];
            *(float4*)&mreg[0] = *(const float4*)&As[k][ty * 8];
            *(float4*)&mreg[4] = *(const float4*)&As[k][ty * 8 + 4];
            *(float4*)&nreg[0] = *(const float4*)&Ws[k][tx * 8];
            *(float4*)&nreg[4] = *(const float4*)&Ws[k][tx * 8 + 4];
#pragma unroll
            for (int i = 0; i < 8; i++)
#pragma unroll
                for (int jj = 0; jj < 8; jj++)
                    acc[i][jj] += mreg[i] * nreg[jj];
        }
    }

    float breg[8];
#pragma unroll
    for (int jj = 0; jj < 8; jj++) {
        const int c = n0 + tx * 8 + jj;
        breg[jj] = (bias && c < N) ? bias[c] : 0.f;
    }
    const int c0 = n0 + tx * 8;
#pragma unroll
    for (int i = 0; i < 8; i++) {
        float* crow = C + (size_t)(m0 + ty * 8 + i) * N;
        if (c0 < N) {
            float4 o = { acc[i][0] + breg[0], acc[i][1] + breg[1],
                         acc[i][2] + breg[2], acc[i][3] + breg[3] };
            *(float4*)(crow + c0) = o;
        }
        if (c0 + 4 < N) {
            float4 o = { acc[i][4] + breg[4], acc[i][5] + breg[5],
                         acc[i][6] + breg[6], acc[i][7] + breg[7] };
            *(float4*)(crow + c0 + 4) = o;
        }
    }
}

// ---------------- GEMM: C = A @ B + bias (pipelined, occ 2) ----------------
__global__ void __launch_bounds__(256, 2)
gemm_ab(const float* __restrict__ A, const float* __restrict__ B,
        const float* __restrict__ bias, float* __restrict__ C,
        int M, int N, int K,
        long long sA, long long sB, long long sC)
{
    A += (size_t)blockIdx.z * sA;
    B += (size_t)blockIdx.z * sB;
    C += (size_t)blockIdx.z * sC;

    __shared__ float As[8][132];
    __shared__ float Bs[8][132];

    const int tid = threadIdx.x;
    const int tx = tid % 16, ty = tid / 16;
    const int m0 = blockIdx.y * 128, n0 = blockIdx.x * 128;
    const int r = tid >> 1, cq = tid & 1;
    const int kk = tid >> 5, nq = tid & 31;

    const float* Aptr = A + (size_t)(m0 + r) * K + cq * 4;
    const bool   bok  = (n0 + nq * 4) < N;
    const float* Bptr = B + (size_t)kk * N + n0 + nq * 4;

    float acc[8][8];
#pragma unroll
    for (int i = 0; i < 8; i++)
#pragma unroll
        for (int jj = 0; jj < 8; jj++) acc[i][jj] = 0.f;

    float4 a4 = *(const float4*)(Aptr);
    float4 b4 = bok ? *(const float4*)(Bptr) : make_float4(0.f,0.f,0.f,0.f);

    for (int k0 = 0; k0 < K; k0 += 8) {
        __syncthreads();
        As[cq * 4 + 0][r] = a4.x; As[cq * 4 + 1][r] = a4.y;
        As[cq * 4 + 2][r] = a4.z; As[cq * 4 + 3][r] = a4.w;
        *(float4*)&Bs[kk][nq * 4] = b4;
        __syncthreads();
        if (k0 + 8 < K) {
            a4 = *(const float4*)(Aptr + k0 + 8);
            b4 = bok ? *(const float4*)(Bptr + (size_t)(k0 + 8) * N)
                     : make_float4(0.f,0.f,0.f,0.f);
        }
#pragma unroll
        for (int k = 0; k < 8; k++) {
            float mreg[8], nreg[8];
            *(float4*)&mreg[0] = *(const float4*)&As[k][ty * 8];
            *(float4*)&mreg[4] = *(const float4*)&As[k][ty * 8 + 4];
            *(float4*)&nreg[0] = *(const float4*)&Bs[k][tx * 8];
            *(float4*)&nreg[4] = *(const float4*)&Bs[k][tx * 8 + 4];
#pragma unroll
            for (int i = 0; i < 8; i++)
#pragma unroll
                for (int jj = 0; jj < 8; jj++)
                    acc[i][jj] += mreg[i] * nreg[jj];
        }
    }

    float breg[8];
#pragma unroll
    for (int jj = 0; jj < 8; jj++) {
        const int c = n0 + tx * 8 + jj;
        breg[jj] = (bias && c < N) ? bias[c] : 0.f;
    }
    const int c0 = n0 + tx * 8;
#pragma unroll
    for (int i = 0; i < 8; i++) {
        float* crow = C + (size_t)(m0 + ty * 8 + i) * N;
        if (c0 < N) {
            float4 o = { acc[i][0] + breg[0], acc[i][1] + breg[1],
                         acc[i][2] + breg[2], acc[i][3] + breg[3] };
            *(float4*)(crow + c0) = o;
        }
        if (c0 + 4 < N) {
            float4 o = { acc[i][4] + breg[4], acc[i][5] + breg[5],
                         acc[i][6] + breg[6], acc[i][7] + breg[7] };
            *(float4*)(crow + c0 + 4) = o;
        }
    }
}

// ---------------- row softmax over 1024 cols ----------------
__global__ void __launch_bounds__(256, 1)
softmax_rows(float* __restrict__ E)
{
    float4* e4 = (float4*)(E + (size_t)blockIdx.x * Sq);
    const int tid = threadIdx.x;
    float4 v = e4[tid];

    float m = fmaxf(fmaxf(v.x, v.y), fmaxf(v.z, v.w));
#pragma unroll
    for (int o = 16; o > 0; o >>= 1)
        m = fmaxf(m, __shfl_xor_sync(0xffffffffu, m, o));
    __shared__ float wredm[8];
    if ((tid & 31) == 0) wredm[tid >> 5] = m;
    __syncthreads();
    float mm = wredm[0];
#pragma unroll
    for (int i = 1; i < 8; i++) mm = fmaxf(mm, wredm[i]);

    v.x = __expf(v.x - mm); v.y = __expf(v.y - mm);
    v.z = __expf(v.z - mm); v.w = __expf(v.w - mm);
    float s = v.x + v.y + v.z + v.w;
#pragma unroll
    for (int o = 16; o > 0; o >>= 1)
        s += __shfl_xor_sync(0xffffffffu, s, o);
    __shared__ float wreds[8];
    if ((tid & 31) == 0) wreds[tid >> 5] = s;
    __syncthreads();
    float ss = 0.f;
#pragma unroll
    for (int i = 0; i < 8; i++) ss += wreds[i];

    const float inv = __fdividef(1.f, ss);
    v.x *= inv; v.y *= inv; v.z *= inv; v.w *= inv;
    e4[tid] = v;
}

__global__ void embed_k(const int* __restrict__ tok, const float* __restrict__ emb)
{
    const int i = blockIdx.x * blockDim.x + threadIdx.x;
    const int n4 = Bq * Sq * Eq / 4;
    if (i < n4) {
        const int row = i / (Eq / 4);
        const int c   = i % (Eq / 4);
        const int t   = tok[row];
        ((float4*)g_x)[i] = ((const float4*)(emb + (size_t)t * Eq))[c];
    }
}

__global__ void ft_k()
{
    const int i = blockIdx.x * blockDim.x + threadIdx.x;
    const int n4 = Bq * Sq * H2q / 4;
    if (i < n4) {
        const float4 a = ((const float4*)g_cfc)[i];
        const float4 b = ((const float4*)g_cfcfc)[i];
        const float4 c = ((const float4*)g_htfc)[i];
        const float4 d = ((const float4*)g_bigru)[i];
        float4 o;
        o.x = a.x * fsig(b.x + c.x) + d.x;
        o.y = a.y * fsig(b.y + c.y) + d.y;
        o.z = a.z * fsig(b.z + c.z) + d.z;
        o.w = a.w * fsig(b.w + c.w) + d.w;
        ((float4*)g_ft)[i] = o;
    }
}

// ---------------- launch ----------------
static float* sym(const void* s) {
    void* p = nullptr;
    cudaGetSymbolAddress(&p, s);
    return (float*)p;
}

extern "C" void kernel_launch(void* const* d_in, const int* in_sizes, int n_in,
                              void* d_out, int out_size)
{
    (void)in_sizes; (void)n_in; (void)out_size;
    const int*   tok     = (const int*)  d_in[0];
    const float* emb     = (const float*)d_in[2];
    const float* wi_f    = (const float*)d_in[3];
    const float* wh_f    = (const float*)d_in[4];
    const float* bi_f    = (const float*)d_in[5];
    const float* bh_f    = (const float*)d_in[6];
    const float* wi_b    = (const float*)d_in[7];
    const float* wh_b    = (const float*)d_in[8];
    const float* bi_b    = (const float*)d_in[9];
    const float* bh_b    = (const float*)d_in[10];
    const float* uwi     = (const float*)d_in[11];
    const float* uwh     = (const float*)d_in[12];
    const float* ubi     = (const float*)d_in[13];
    const float* ubh     = (const float*)d_in[14];
    const float* w_attn  = (const float*)d_in[15];
    const float* b_attn  = (const float*)d_in[16];
    const float* w_afc   = (const float*)d_in[17];
    const float* b_afc   = (const float*)d_in[18];
    const float* w_ht    = (const float*)d_in[19];
    const float* b_ht    = (const float*)d_in[20];
    const float* w_out   = (const float*)d_in[21];
    const float* b_out   = (const float*)d_in[22];
    float* out = (float*)d_out;

    float* x     = sym(g_x);
    float* xgf   = sym(g_xgf);
    float* xgb   = sym(g_xgb);
    float* bigru = sym(g_bigru);
    float* xgu   = sym(g_xgu);
    float* U     = sym(g_U);
    float* energ = sym(g_energ);
    float* ctx   = sym(g_ctx);
    float* cfc   = sym(g_cfc);
    float* cfcfc = sym(g_cfcfc);
    float* htfc  = sym(g_htfc);
    float* ft    = sym(g_ft);

    const long long sU = (long long)Sq * H2q;
    const long long sE = (long long)Sq * Sq;
    const int M = Bq * Sq;                      // 8192

    embed_k<<<(Bq*Sq*Eq/4 + 255)/256, 256>>>(tok, emb);

    gemm_abt<<<dim3(6, 64, 1), 256>>>(x, wi_f, bi_f, xgf, M, 3*Hq, Eq, 0, 0, 0);
    gemm_abt<<<dim3(6, 64, 1), 256>>>(x, wi_b, bi_b, xgb, M, 3*Hq, Eq, 0, 0, 0);

    scan_fb<<<128, 192>>>(xgf, xgb, wh_f, bh_f, wh_b, bh_b);

    gemm_abt<<<dim3(12, 64, 1), 256>>>(bigru, uwi, ubi, xgu, M, 3*H2q, H2q, 0, 0, 0);

    scan_uni<<<128, 192>>>(xgu, uwh, ubh);

    gemm_abt<<<dim3(8, 8, Bq), 256>>>(U, bigru, nullptr, energ,
                                      Sq, Sq, H2q, sU, sU, sE);
    softmax_rows<<<M, 256>>>(energ);
    gemm_ab<<<dim3(4, 8, Bq), 256>>>(energ, bigru, nullptr, ctx,
                                     Sq, H2q, Sq, sE, sU, sU);

    gemm_abt<<<dim3(4, 64, 1), 256>>>(ctx,   w_attn, b_attn, cfc,   M, H2q, H2q, 0, 0, 0);
    gemm_abt<<<dim3(4, 64, 1), 256>>>(cfc,   w_afc,  b_afc,  cfcfc, M, H2q, H2q, 0, 0, 0);
    gemm_abt<<<dim3(4, 64, 1), 256>>>(bigru, w_ht,   b_ht,   htfc,  M, H2q, H2q, 0, 0, 0);

    ft_k<<<(Bq*Sq*H2q/4 + 255)/256, 256>>>();

    gemm_abt<<<dim3(1, 64, 1), 256>>>(ft, w_out, b_out, out, M, Cq, H2q, 0, 0, 0);
}